// round 6
// baseline (speedup 1.0000x reference)
#include <cuda_runtime.h>
#include <math_constants.h>
#include <cstdint>

#define E_TOT 50000
#define E_PAD 50048
#define DD 128
#define HH 256
#define BB 8
#define KTOP 10
#define TILE_M 128
#define N_TILES ((E_TOT + TILE_M - 1) / TILE_M)   // 391

__device__ float g_ph[BB * HH];
__device__ float g_part[2][BB][E_PAD];

// ---------------------------------------------------------------------------
__device__ __forceinline__ float tf32_rna(float x) {
    uint32_t u;
    asm("cvt.rna.tf32.f32 %0, %1;" : "=r"(u) : "f"(x));
    return __uint_as_float(u);
}
__device__ __forceinline__ void mma_tf32(float c[4], const uint32_t a[4],
                                         uint32_t b0, uint32_t b1) {
    asm volatile(
        "mma.sync.aligned.m16n8k8.row.col.f32.tf32.tf32.f32 "
        "{%0,%1,%2,%3}, {%4,%5,%6,%7}, {%8,%9}, {%0,%1,%2,%3};"
        : "+f"(c[0]), "+f"(c[1]), "+f"(c[2]), "+f"(c[3])
        : "r"(a[0]), "r"(a[1]), "r"(a[2]), "r"(a[3]), "r"(b0), "r"(b1));
}

// ---------------------------------------------------------------------------
// Kernel 1: ph[b][h]
// ---------------------------------------------------------------------------
__global__ void ph_kernel(const int* __restrict__ head, const int* __restrict__ rel,
                          const float* __restrict__ ent, const float* __restrict__ relm,
                          const float* __restrict__ W1, const float* __restrict__ b1) {
    __shared__ float red[4 * 64];
    const int b  = blockIdx.x;
    const int hl = threadIdx.x & 63;
    const int dq = threadIdx.x >> 6;
    const int h  = blockIdx.y * 64 + hl;
    const float* hrow = ent  + (size_t)head[b] * DD;
    const float* rrow = relm + (size_t)rel[b] * DD;
    float acc = 0.f;
#pragma unroll 8
    for (int dd = 0; dd < 32; ++dd) {
        int d = dq * 32 + dd;
        acc = fmaf(hrow[d], W1[d * HH + h], acc);
        acc = fmaf(rrow[d], W1[(DD + d) * HH + h], acc);
    }
    red[dq * 64 + hl] = acc;
    __syncthreads();
    if (threadIdx.x < 64)
        g_ph[b * HH + h] = red[hl] + red[64 + hl] + red[128 + hl] + red[192 + hl] + b1[h];
}

// ---------------------------------------------------------------------------
// Kernel 2: 3xTF32 mma.sync GEMM + fused relu-score epilogue.
// grid (391, 2): x = 128-entity tile, y = n-half (128 of 256 h).
// Raw fp32 staged in smem (double-buffered); tf32 hi/lo split in registers.
// ---------------------------------------------------------------------------
#define A_STRIDE 36      // 32 k + 4 pad
#define B_STRIDE 136     // 128 n + 8 pad
#define A_CH (128 * A_STRIDE)       // 4608 f
#define B_CH (32 * B_STRIDE)        // 4352 f
#define SM_A 0                      // 2 buffers
#define SM_B (2 * A_CH)             // 2 buffers
#define SM_PH (2 * A_CH + 2 * B_CH)
#define SM_W2 (SM_PH + BB * 128)
#define SM_TOT_F (SM_W2 + 128)      // 19072 f = 76.3 KB

extern __shared__ float sm[];

__device__ __forceinline__ void stage_chunk(const float* __restrict__ ent,
                                            const float* __restrict__ W1t,
                                            int e_base, int nh, int c, int buf,
                                            int tid) {
    float* A = sm + SM_A + buf * A_CH;
    float* B = sm + SM_B + buf * B_CH;
#pragma unroll
    for (int it = 0; it < 4; ++it) {
        int idx = it * 256 + tid;
        int m  = idx >> 3;
        int k4 = idx & 7;
        float4 v = make_float4(0.f, 0.f, 0.f, 0.f);
        if (e_base + m < E_TOT)
            v = *(const float4*)(ent + (size_t)(e_base + m) * DD + c * 32 + k4 * 4);
        *(float4*)(A + m * A_STRIDE + k4 * 4) = v;
    }
#pragma unroll
    for (int it = 0; it < 4; ++it) {
        int idx = it * 256 + tid;
        int kk = idx >> 5;
        int n4 = idx & 31;
        float4 v = *(const float4*)(W1t + (size_t)(c * 32 + kk) * HH + nh * 128 + n4 * 4);
        *(float4*)(B + kk * B_STRIDE + n4 * 4) = v;
    }
}

__global__ __launch_bounds__(256, 2)
void score_kernel(const float* __restrict__ ent, const float* __restrict__ W1,
                  const float* __restrict__ W2) {
    const int tid = threadIdx.x;
    const int wid = tid >> 5;
    const int lid = tid & 31;
    const int gID = lid >> 2;
    const int tig = lid & 3;
    const int mw  = wid & 3;
    const int nw  = wid >> 2;
    const int e_base = blockIdx.x * TILE_M;
    const int nh = blockIdx.y;

    float* ph_s = sm + SM_PH;
    float* w2_s = sm + SM_W2;

    for (int idx = tid; idx < BB * 128; idx += 256) {
        int b = idx >> 7, col = idx & 127;
        ph_s[idx] = g_ph[b * HH + nh * 128 + col];
    }
    if (tid < 128) w2_s[tid] = W2[nh * 128 + tid];

    float acc[2][8][4];
#pragma unroll
    for (int mt = 0; mt < 2; ++mt)
#pragma unroll
        for (int nt = 0; nt < 8; ++nt)
#pragma unroll
            for (int q = 0; q < 4; ++q) acc[mt][nt][q] = 0.f;

    const float* W1t = W1 + 2 * DD * HH;

    stage_chunk(ent, W1t, e_base, nh, 0, 0, tid);
    __syncthreads();

    for (int c = 0; c < 4; ++c) {
        const int buf = c & 1;
        if (c < 3) stage_chunk(ent, W1t, e_base, nh, c + 1, buf ^ 1, tid);

        const float* A = sm + SM_A + buf * A_CH;
        const float* B = sm + SM_B + buf * B_CH;

#pragma unroll
        for (int s = 0; s < 4; ++s) {
            const int ks = s * 8;
            uint32_t ahi[2][4], alo[2][4];
#pragma unroll
            for (int mt = 0; mt < 2; ++mt) {
                int r = mw * 32 + mt * 16 + gID;
                float v0 = A[r * A_STRIDE + ks + tig];
                float v1 = A[(r + 8) * A_STRIDE + ks + tig];
                float v2 = A[r * A_STRIDE + ks + tig + 4];
                float v3 = A[(r + 8) * A_STRIDE + ks + tig + 4];
                float h0 = tf32_rna(v0), h1 = tf32_rna(v1);
                float h2 = tf32_rna(v2), h3 = tf32_rna(v3);
                ahi[mt][0] = __float_as_uint(h0);
                ahi[mt][1] = __float_as_uint(h1);
                ahi[mt][2] = __float_as_uint(h2);
                ahi[mt][3] = __float_as_uint(h3);
                alo[mt][0] = __float_as_uint(tf32_rna(v0 - h0));
                alo[mt][1] = __float_as_uint(tf32_rna(v1 - h1));
                alo[mt][2] = __float_as_uint(tf32_rna(v2 - h2));
                alo[mt][3] = __float_as_uint(tf32_rna(v3 - h3));
            }
#pragma unroll
            for (int nt = 0; nt < 8; ++nt) {
                int col = nw * 64 + nt * 8 + gID;
                float w0 = B[(ks + tig) * B_STRIDE + col];
                float w1 = B[(ks + tig + 4) * B_STRIDE + col];
                float h0 = tf32_rna(w0), h1 = tf32_rna(w1);
                uint32_t b0h = __float_as_uint(h0);
                uint32_t b1h = __float_as_uint(h1);
                uint32_t b0l = __float_as_uint(tf32_rna(w0 - h0));
                uint32_t b1l = __float_as_uint(tf32_rna(w1 - h1));
#pragma unroll
                for (int mt = 0; mt < 2; ++mt) {
                    mma_tf32(acc[mt][nt], ahi[mt], b0h, b1h);
                    mma_tf32(acc[mt][nt], ahi[mt], b0l, b1l);
                    mma_tf32(acc[mt][nt], alo[mt], b0h, b1h);
                }
            }
        }
        __syncthreads();
    }

    // ---- epilogue: relu-score on C fragments, quad-reduce, nw-combine ----
    float2 w2v[8];
#pragma unroll
    for (int nt = 0; nt < 8; ++nt)
        w2v[nt] = *(float2*)(w2_s + nw * 64 + nt * 8 + tig * 2);

    float* part_s = sm + SM_A;   // reuse A buffers: [2(nw)][BB][128]
#pragma unroll
    for (int b = 0; b < BB; ++b) {
        float s00 = 0.f, s01 = 0.f, s10 = 0.f, s11 = 0.f;
#pragma unroll
        for (int nt = 0; nt < 8; ++nt) {
            float2 p2 = *(float2*)(ph_s + b * 128 + nw * 64 + nt * 8 + tig * 2);
            float wx = w2v[nt].x, wy = w2v[nt].y;
            s00 = fmaf(fmaxf(acc[0][nt][0] + p2.x, 0.f), wx, s00);
            s00 = fmaf(fmaxf(acc[0][nt][1] + p2.y, 0.f), wy, s00);
            s01 = fmaf(fmaxf(acc[0][nt][2] + p2.x, 0.f), wx, s01);
            s01 = fmaf(fmaxf(acc[0][nt][3] + p2.y, 0.f), wy, s01);
            s10 = fmaf(fmaxf(acc[1][nt][0] + p2.x, 0.f), wx, s10);
            s10 = fmaf(fmaxf(acc[1][nt][1] + p2.y, 0.f), wy, s10);
            s11 = fmaf(fmaxf(acc[1][nt][2] + p2.x, 0.f), wx, s11);
            s11 = fmaf(fmaxf(acc[1][nt][3] + p2.y, 0.f), wy, s11);
        }
#pragma unroll
        for (int off = 1; off <= 2; off <<= 1) {
            s00 += __shfl_xor_sync(0xffffffffu, s00, off);
            s01 += __shfl_xor_sync(0xffffffffu, s01, off);
            s10 += __shfl_xor_sync(0xffffffffu, s10, off);
            s11 += __shfl_xor_sync(0xffffffffu, s11, off);
        }
        if (tig == 0) {
            int r0 = mw * 32 + gID;
            int r1 = mw * 32 + 16 + gID;
            part_s[(nw * BB + b) * 128 + r0]     = s00;
            part_s[(nw * BB + b) * 128 + r0 + 8] = s01;
            part_s[(nw * BB + b) * 128 + r1]     = s10;
            part_s[(nw * BB + b) * 128 + r1 + 8] = s11;
        }
    }
    __syncthreads();

    // combine nw halves: 1024 (b,row) pairs over 256 threads
#pragma unroll
    for (int it = 0; it < 4; ++it) {
        int idx = it * 256 + tid;        // b*128 + row
        int b = idx >> 7, row = idx & 127;
        g_part[nh][b][e_base + row] =
            part_s[(0 * BB + b) * 128 + row] + part_s[(1 * BB + b) * 128 + row];
    }
}

// ---------------------------------------------------------------------------
// Kernel 3: fused top-10. grid (8), block 512.
// ---------------------------------------------------------------------------
__global__ __launch_bounds__(512)
void topk_kernel(const float* __restrict__ b2, float* __restrict__ out) {
    const int b = blockIdx.x;
    const int tid = threadIdx.x;
    const float b2v = b2[0];

    float sc[KTOP];
    int   si[KTOP];
#pragma unroll
    for (int j = 0; j < KTOP; ++j) { sc[j] = -CUDART_INF_F; si[j] = 0x7fffffff; }

    for (int e = tid; e < E_TOT; e += 512) {
        float s = g_part[0][b][e] + g_part[1][b][e] + b2v;
        if (s > sc[KTOP - 1]) {
            int p = KTOP - 1;
            while (p > 0 && s > sc[p - 1]) { sc[p] = sc[p - 1]; si[p] = si[p - 1]; --p; }
            sc[p] = s; si[p] = e;
        }
    }

    __shared__ float ssc[512 * KTOP];
    __shared__ int   ssi[512 * KTOP];
#pragma unroll
    for (int j = 0; j < KTOP; ++j) { ssc[tid * KTOP + j] = sc[j]; ssi[tid * KTOP + j] = si[j]; }
    __syncthreads();

    for (int stride = 256; stride > 0; stride >>= 1) {
        if (tid < stride) {
            float* A  = &ssc[tid * KTOP];
            int*   Ai = &ssi[tid * KTOP];
            float* Bv = &ssc[(tid + stride) * KTOP];
            int*   Bi = &ssi[(tid + stride) * KTOP];
            float msc[KTOP]; int msi[KTOP];
            int p = 0, q = 0;
#pragma unroll
            for (int j = 0; j < KTOP; ++j) {
                bool takeA = (A[p] > Bv[q]) || (A[p] == Bv[q] && Ai[p] < Bi[q]);
                if (takeA) { msc[j] = A[p]; msi[j] = Ai[p]; ++p; }
                else       { msc[j] = Bv[q]; msi[j] = Bi[q]; ++q; }
            }
#pragma unroll
            for (int j = 0; j < KTOP; ++j) { A[j] = msc[j]; Ai[j] = msi[j]; }
        }
        __syncthreads();
    }

    if (tid < KTOP) {
        out[b * KTOP + tid]             = (float)ssi[tid];   // top_indices
        out[BB * KTOP + b * KTOP + tid] = ssc[tid];          // top_scores
    }
}

// ---------------------------------------------------------------------------
extern "C" void kernel_launch(void* const* d_in, const int* in_sizes, int n_in,
                              void* d_out, int out_size) {
    int base = (n_in >= 3 && in_sizes[2] == 1) ? 3 : 2;

    const int*   head = (const int*)d_in[0];
    const int*   rel  = (const int*)d_in[1];
    const float* ent  = (const float*)d_in[base + 0];
    const float* relm = (const float*)d_in[base + 1];
    const float* W1   = (const float*)d_in[base + 2];
    const float* b1   = (const float*)d_in[base + 3];
    const float* W2   = (const float*)d_in[base + 4];
    const float* b2   = (const float*)d_in[base + 5];
    float* out = (float*)d_out;

    size_t smem_bytes = SM_TOT_F * sizeof(float);   // 76.3 KB
    cudaFuncSetAttribute(score_kernel, cudaFuncAttributeMaxDynamicSharedMemorySize,
                         (int)smem_bytes);

    ph_kernel<<<dim3(BB, 4), 256>>>(head, rel, ent, relm, W1, b1);
    score_kernel<<<dim3(N_TILES, 2), 256, smem_bytes>>>(ent, W1, W2);
    topk_kernel<<<BB, 512>>>(b2, out);
}